// round 6
// baseline (speedup 1.0000x reference)
#include <cuda_runtime.h>

// iPUNet forward, two-kernel design.
//
// Kernel 1 (precompute): Y[n][j] for n in [0,2048), j in [0,27):
//   j<21 : feat[n] . W_unet[:, j/3, j%3]   (query-independent grid projections)
//   j=21..23 : feat[n] . W0[j-21] + b0     (raw oris)
//   j=24..26 : feat[n] . W1[j-24] + b1     (raw nors)
// Kernel 2 (main): per-point CTA does ball query, rotation, cell scatter,
//   then feat_off is just a 3-float gather from Y per winning cell.
//
// Shapes: B=2, N=1024, FEAT=128, NSAMPLE=48, GRID=7, RADIUS=0.3
// Output (f32, 417792 elems):
//   oris [0,6144) | nors [6144,12288) | pts_ups [12288,110592)
//   pts_offset [110592,116736) | pts_up [116736,417792)

#define NPTS   1024
#define FEATD  128
#define NS     48
#define YSTR   28          // padded row stride of Y

#define OFF_ORIS   0
#define OFF_NORS   6144
#define OFF_UPS    12288
#define OFF_OFFSET 110592
#define OFF_PTSUP  116736

__device__ float g_Y[2048 * YSTR];

// ---------------------------------------------------------------------------
// Kernel 1: dense precompute (55296 threads, one 128-dot each)
// ---------------------------------------------------------------------------
__global__ __launch_bounds__(128)
void precompute_kernel(const float* __restrict__ feat,
                       const float* __restrict__ Wu,
                       const float* __restrict__ W0, const float* __restrict__ b0,
                       const float* __restrict__ W1, const float* __restrict__ b1)
{
    int idx = blockIdx.x * 128 + threadIdx.x;
    if (idx >= 2048 * 27) return;
    int n = idx / 27;
    int j = idx - n * 27;

    const float* f = feat + (n << 7);
    const float* w;
    int stride;
    float acc;
    if (j < 21)      { w = Wu + j;              stride = 21; acc = 0.0f; }
    else if (j < 24) { w = W0 + ((j - 21) << 7); stride = 1; acc = __ldg(&b0[j - 21]); }
    else             { w = W1 + ((j - 24) << 7); stride = 1; acc = __ldg(&b1[j - 24]); }

#pragma unroll 8
    for (int c = 0; c < FEATD; c++)
        acc += __ldg(&f[c]) * __ldg(&w[c * stride]);

    g_Y[n * YSTR + j] = acc;
}

// ---------------------------------------------------------------------------
// Kernel 2: main fused kernel, one CTA (128 thr) per point
// ---------------------------------------------------------------------------
__global__ __launch_bounds__(128)
void ipunet_kernel(const float* __restrict__ xyz,
                   const int* __restrict__ g_index,
                   float* __restrict__ out)
{
    const int p    = blockIdx.x;       // global point id 0..2047
    const int b    = p >> 10;
    const int pid  = p & 1023;
    const int t    = threadIdx.x;      // 0..127
    const int lane = t & 31;
    const int warp = t >> 5;           // 0..3

    __shared__ float    s_rot[9];
    __shared__ unsigned s_mask[32];
    __shared__ int      s_nbr[NS];
    __shared__ int      s_win[91];
    __shared__ int      s_cnt;
    __shared__ float    s_off[49 * 3];
    __shared__ unsigned s_upmask[49];   // bit q set iff index[q]==s

    // ---- center --------------------------------------------------------------
    const float* xb = xyz + b * 3 * NPTS;
    const float cx = __ldg(&xb[pid]);
    const float cy = __ldg(&xb[NPTS + pid]);
    const float cz = __ldg(&xb[2 * NPTS + pid]);
    const float c2 = cx * cx + cy * cy + cz * cz;

    // ---- smem init -------------------------------------------------------------
    if (t < 91) s_win[t] = -1;
    if (t < 49) s_upmask[t] = 0u;
    s_off[t] = 0.0f;
    if (t < 19) s_off[128 + t] = 0.0f;

    // ---- ball query: 1024-bit mask via ballot ----------------------------------
#pragma unroll
    for (int seg = 0; seg < 8; seg++) {
        int j = seg * 128 + t;
        float px = __ldg(&xb[j]);
        float py = __ldg(&xb[NPTS + j]);
        float pz = __ldg(&xb[2 * NPTS + j]);
        float d = -2.0f * (cx * px + cy * py + cz * pz) + c2
                  + (px * px + py * py + pz * pz);
        unsigned m = __ballot_sync(0xffffffffu, !(d > 0.09f));
        if (lane == 0) s_mask[seg * 4 + warp] = m;
    }
    __syncthreads();

    // ---- concurrent: rotation (t==32) | extraction (warp 0) | upmask (warp 2) --
    if (t >= 64 && t < 80)
        atomicOr(&s_upmask[__ldg(&g_index[t - 64])], 1u << (t - 64));

    if (t == 32) {
        const float* yp = g_Y + p * YSTR + 21;
        float ov[3] = { yp[0], yp[1], yp[2] };
        float nv[3] = { yp[3], yp[4], yp[5] };

        float io = 1.0f / (sqrtf(ov[0]*ov[0]+ov[1]*ov[1]+ov[2]*ov[2] + 1e-8f) + 1e-10f);
        ov[0] *= io; ov[1] *= io; ov[2] *= io;
        float in = 1.0f / (sqrtf(nv[0]*nv[0]+nv[1]*nv[1]+nv[2]*nv[2] + 1e-8f) + 1e-10f);
        nv[0] *= in; nv[1] *= in; nv[2] *= in;

        float r90[3];
        r90[0] = ov[1]*nv[2] - ov[2]*nv[1];
        r90[1] = ov[2]*nv[0] - ov[0]*nv[2];
        r90[2] = ov[0]*nv[1] - ov[1]*nv[0];
        float ir = 1.0f / (sqrtf(r90[0]*r90[0]+r90[1]*r90[1]+r90[2]*r90[2] + 1e-8f) + 1e-10f);
        r90[0] *= ir; r90[1] *= ir; r90[2] *= ir;

        float o0[3];
        o0[0] = r90[1]*nv[2] - r90[2]*nv[1];
        o0[1] = r90[2]*nv[0] - r90[0]*nv[2];
        o0[2] = r90[0]*nv[1] - r90[1]*nv[0];
        float i0 = 1.0f / (sqrtf(o0[0]*o0[0]+o0[1]*o0[1]+o0[2]*o0[2] + 1e-8f) + 1e-10f);
        o0[0] *= i0; o0[1] *= i0; o0[2] *= i0;

        s_rot[0] = o0[0];  s_rot[1] = o0[1];  s_rot[2] = o0[2];
        s_rot[3] = r90[0]; s_rot[4] = r90[1]; s_rot[5] = r90[2];
        s_rot[6] = nv[0];  s_rot[7] = nv[1];  s_rot[8] = nv[2];

#pragma unroll
        for (int d = 0; d < 3; d++) {
            out[OFF_ORIS + p * 3 + d] = ov[d];
            out[OFF_NORS + p * 3 + d] = nv[d];
        }
    }
    if (warp == 0) {
        unsigned m = s_mask[lane];
        int pc = __popc(m);
        int incl = pc;
#pragma unroll
        for (int o = 1; o < 32; o <<= 1) {
            int v = __shfl_up_sync(0xffffffffu, incl, o);
            if (lane >= o) incl += v;
        }
        int excl = incl - pc;
        if (lane == 31) s_cnt = (incl < NS) ? incl : NS;
        unsigned mm = m;
        int r = excl;
        while (mm && r < NS) {
            int bpos = __ffs(mm) - 1;
            s_nbr[r] = (lane << 5) + bpos;
            mm &= mm - 1;
            r++;
        }
    }
    __syncthreads();

    // ---- local coords -> cell; last-wins winner ---------------------------------
    int myCell = -1, myJ = 0;
    if (t < NS) {
        myJ = (t < s_cnt) ? s_nbr[t] : s_nbr[0];
        float lx = __ldg(&xb[myJ]) - cx;
        float ly = __ldg(&xb[NPTS + myJ]) - cy;
        float lz = __ldg(&xb[2 * NPTS + myJ]) - cz;
        int c[3];
#pragma unroll
        for (int d = 0; d < 3; d++) {
            float lp = lx * s_rot[d*3+0] + ly * s_rot[d*3+1] + lz * s_rot[d*3+2];
            float v = rintf((lp + 0.3f) / 0.6f * 6.0f);
            int ci = (int)v;
            ci = ci < 0 ? 0 : (ci > 6 ? 6 : ci);
            c[d] = ci;
        }
        myCell = c[0] * 7 + c[1] * 7 + c[2];   // reference quirk: both *g
        atomicMax(&s_win[myCell], t);
    }
    __syncthreads();

    // ---- winners gather precomputed Y row (3 floats) + accumulate --------------
    if (t < NS && s_win[myCell] == t) {
        int k  = myCell % 7;
        int p5 = (myCell / 49) * 7 + (myCell / 7) % 7;
        const float* y = g_Y + ((b << 10) + myJ) * YSTR + k * 3;
        atomicAdd(&s_off[p5 * 3 + 0], y[0]);
        atomicAdd(&s_off[p5 * 3 + 1], y[1]);
        atomicAdd(&s_off[p5 * 3 + 2], y[2]);
    }
    __syncthreads();

    // ---- up = vals + feat_off; rotate back; write outputs ----------------------
    if (t < 49) {
        int s = t;
        float u0 = (float)(s / 7 - 3) * 0.1f + s_off[s * 3 + 0];
        float u1 = (float)(s % 7 - 3) * 0.1f + s_off[s * 3 + 1];
        float u2 = s_off[s * 3 + 2];
        float w[3];
#pragma unroll
        for (int d = 0; d < 3; d++)
            w[d] = u0 * s_rot[d] + u1 * s_rot[3 + d] + u2 * s_rot[6 + d]
                 + (d == 0 ? cx : (d == 1 ? cy : cz));

        float* o_up = out + OFF_PTSUP + (p * 49 + s) * 3;
        o_up[0] = w[0]; o_up[1] = w[1]; o_up[2] = w[2];

        if (s == 24) {
            float* o_of = out + OFF_OFFSET + p * 3;
            o_of[0] = w[0]; o_of[1] = w[1]; o_of[2] = w[2];
        }
        unsigned m = s_upmask[s];
        while (m) {
            int q = __ffs(m) - 1;
            m &= m - 1;
            float* o_u = out + OFF_UPS + (p * 16 + q) * 3;
            o_u[0] = w[0]; o_u[1] = w[1]; o_u[2] = w[2];
        }
    }
}

extern "C" void kernel_launch(void* const* d_in, const int* in_sizes, int n_in,
                              void* d_out, int out_size)
{
    const float* xyz   = (const float*)d_in[0];
    const float* feat  = (const float*)d_in[1];
    const float* W0    = (const float*)d_in[2];
    const float* b0    = (const float*)d_in[3];
    const float* W1    = (const float*)d_in[4];
    const float* b1    = (const float*)d_in[5];
    const float* Wu    = (const float*)d_in[6];
    const int*   index = (const int*)d_in[7];
    float* out = (float*)d_out;

    precompute_kernel<<<(2048 * 27 + 127) / 128, 128>>>(feat, Wu, W0, b0, W1, b1);
    ipunet_kernel<<<2048, 128>>>(xyz, index, out);
}